// round 1
// baseline (speedup 1.0000x reference)
#include <cuda_runtime.h>

#define BATCH 8
#define NTOK  16384
#define DIMC  64
#define NK    256
#define SCALE 0.125f

// Scratch (allocation-free rule: __device__ globals)
__device__ float g_w3[32 * 8448];        // staged conv weights: [stage][o][132 pad]
__device__ float g_k[BATCH * 64 * NK];   // k transposed: [b][c][p]
__device__ float g_v[BATCH * NK * 64];   // v: [b][p][c]

// ---------------------------------------------------------------------------
// Kernel 0: reshuffle sr_w [O=64, I=64, KH=8, KW=8] into stage-major padded
// layout so prep-kernel smem fills are linear float4 copies.
// stage = ic*8 + kh (ic: 16-wide input-channel chunk). slab = [o][kw*16+ii] pad 132.
// ---------------------------------------------------------------------------
__global__ void k_transpose_w(const float* __restrict__ srw) {
    int d = blockIdx.x * 512 + threadIdx.x;   // 528*512 = 270336 = 32*8448 exactly
    int stage = d / 8448;
    int r = d - stage * 8448;
    int o = r / 132;
    int r2 = r - o * 132;
    float v = 0.f;
    if (r2 < 128) {
        int kw = r2 >> 4, ii = r2 & 15;
        int ic = stage >> 3, kh = stage & 7;
        int i = ic * 16 + ii;
        v = srw[o * 4096 + i * 64 + kh * 8 + kw];
    }
    g_w3[d] = v;
}

// ---------------------------------------------------------------------------
// Kernel 1: sr-conv (k=s=8) + LayerNorm + KV projection.
// grid (16 ph, 8 b), 512 threads. Each CTA: 16 patches (one ph row) x 64 out ch.
// ---------------------------------------------------------------------------
__global__ void __launch_bounds__(512) k_prep(
    const float* __restrict__ x, const float* __restrict__ srb,
    const float* __restrict__ lng, const float* __restrict__ lnb,
    const float* __restrict__ Wkv)
{
    __shared__ float ws[8448];   // weight slab (o*132 + kw*16 + ii)
    __shared__ float xs[2048];   // x row-group chunk [w=128][ii=16]
    int ph = blockIdx.x, b = blockIdx.y;
    int t = threadIdx.x;
    int o = t & 63, pwg = t >> 6;      // pwg 0..7 ; this thread owns pw = pwg and pwg+8

    float a0 = 0.f, a1 = 0.f;
    const float4* w3_4 = (const float4*)g_w3;
    float4* ws4s = (float4*)ws;
    float4* xs4s = (float4*)xs;

    for (int stage = 0; stage < 32; stage++) {
        int ic = stage >> 3, kh = stage & 7;
        __syncthreads();
        for (int d4 = t; d4 < 2112; d4 += 512)
            ws4s[d4] = w3_4[stage * 2112 + d4];
        {
            int w = t >> 2, j = t & 3;
            int row = (ph * 8 + kh) * 128 + w;
            xs4s[t] = ((const float4*)x)[(b * NTOK + row) * 16 + ic * 4 + j];
        }
        __syncthreads();
        const float4* wsb = (const float4*)ws + o * 33;   // o*132/4
        #pragma unroll
        for (int kw = 0; kw < 8; kw++) {
            #pragma unroll
            for (int ii4 = 0; ii4 < 4; ii4++) {
                float4 w  = wsb[kw * 4 + ii4];
                float4 xa = xs4s[(pwg * 8 + kw) * 4 + ii4];
                float4 xb = xs4s[((pwg + 8) * 8 + kw) * 4 + ii4];
                a0 = fmaf(w.x, xa.x, a0); a0 = fmaf(w.y, xa.y, a0);
                a0 = fmaf(w.z, xa.z, a0); a0 = fmaf(w.w, xa.w, a0);
                a1 = fmaf(w.x, xb.x, a1); a1 = fmaf(w.y, xb.y, a1);
                a1 = fmaf(w.z, xb.z, a1); a1 = fmaf(w.w, xb.w, a1);
            }
        }
    }
    __syncthreads();

    // conv outputs -> smem (reuse ws region)
    float* co = ws;          // [16][64]
    float* ln = ws + 1024;   // [16][64]
    float bo = srb[o];
    co[pwg * 64 + o]       = a0 + bo;
    co[(pwg + 8) * 64 + o] = a1 + bo;
    __syncthreads();

    // LayerNorm: warp w handles patch row w (16 warps, 16 rows)
    int warp = t >> 5, lane = t & 31;
    {
        float v0 = co[warp * 64 + lane];
        float v1 = co[warp * 64 + lane + 32];
        float s = v0 + v1, sq = v0 * v0 + v1 * v1;
        #pragma unroll
        for (int off = 16; off; off >>= 1) {
            s  += __shfl_xor_sync(0xffffffffu, s, off);
            sq += __shfl_xor_sync(0xffffffffu, sq, off);
        }
        float mean = s * (1.f / 64.f);
        float var  = sq * (1.f / 64.f) - mean * mean;
        float rs = rsqrtf(var + 1e-5f);
        ln[warp * 64 + lane]      = (v0 - mean) * rs * lng[lane]      + lnb[lane];
        ln[warp * 64 + lane + 32] = (v1 - mean) * rs * lng[lane + 32] + lnb[lane + 32];
    }
    __syncthreads();

    // KV: [16 patches] x [128 out] ; thread: c = t&127, 4 patches
    int c = t & 127, pg = t >> 7;   // pg 0..3
    float acc[4] = {0.f, 0.f, 0.f, 0.f};
    for (int i = 0; i < 64; i++) {
        float wv = Wkv[i * 128 + c];
        #pragma unroll
        for (int m = 0; m < 4; m++)
            acc[m] = fmaf(ln[(pg * 4 + m) * 64 + i], wv, acc[m]);
    }
    #pragma unroll
    for (int m = 0; m < 4; m++) {
        int p = ph * 16 + pg * 4 + m;
        if (c < 64) g_k[(b * 64 + c) * NK + p]        = acc[m];  // transposed
        else        g_v[(b * NK + p) * 64 + (c - 64)] = acc[m];
    }
}

// ---------------------------------------------------------------------------
// Kernel 2: fused q-proj + attention + softmax + ctx + out-proj.
// grid (256 qtiles, 8 b), 512 threads, 209 KB dynamic smem (1 CTA/SM).
// ---------------------------------------------------------------------------
__device__ __forceinline__ void softmax_write(float* acc, float* S, int qi, int lane) {
    float m = acc[0];
    #pragma unroll
    for (int j = 1; j < 8; j++) m = fmaxf(m, acc[j]);
    #pragma unroll
    for (int off = 16; off; off >>= 1) m = fmaxf(m, __shfl_xor_sync(0xffffffffu, m, off));
    float s = 0.f;
    #pragma unroll
    for (int j = 0; j < 8; j++) { acc[j] = __expf((acc[j] - m) * SCALE); s += acc[j]; }
    #pragma unroll
    for (int off = 16; off; off >>= 1) s += __shfl_xor_sync(0xffffffffu, s, off);
    float inv = 1.f / s;
    float4* S4 = (float4*)(S + qi * 260 + lane * 8);
    S4[0] = make_float4(acc[0] * inv, acc[1] * inv, acc[2] * inv, acc[3] * inv);
    S4[1] = make_float4(acc[4] * inv, acc[5] * inv, acc[6] * inv, acc[7] * inv);
}

__global__ void __launch_bounds__(512, 1) k_attn(
    const float* __restrict__ x, const float* __restrict__ Wq,
    const float* __restrict__ Wp, const float* __restrict__ bp,
    float* __restrict__ out)
{
    extern __shared__ float sm[];
    float* ks = sm;            // [64][256]  kT
    float* vs = sm + 16384;    // [256][64]
    float* S  = sm + 32768;    // [64][260]  scores/probs (x-staging first)
    float* qs = sm + 49408;    // [64][64]   q, later ctx

    int t = threadIdx.x;
    int qt = blockIdx.x, b = blockIdx.y;
    int q0 = qt * 64;

    float4* ks4 = (float4*)ks;
    float4* vs4 = (float4*)vs;
    float4* Sx4 = (float4*)S;
    const float4* gk4 = (const float4*)g_k + b * 4096;
    const float4* gv4 = (const float4*)g_v + b * 4096;
    const float4* gx4 = (const float4*)x + (size_t)(b * NTOK + q0) * 16;
    for (int i = t; i < 4096; i += 512) { ks4[i] = gk4[i]; vs4[i] = gv4[i]; }
    for (int i = t; i < 1024; i += 512) Sx4[i] = gx4[i];
    __syncthreads();

    // --- q = x @ Wq : thread -> (qi = t>>3, 8 output cols) ---
    {
        int qi = t >> 3, cg = t & 7;
        float4 acc0 = {0,0,0,0}, acc1 = {0,0,0,0};
        const float4* wq4 = (const float4*)Wq;
        const float* Sx = S;
        for (int i = 0; i < 64; i++) {
            float xv = Sx[qi * 64 + i];
            float4 w0 = wq4[i * 16 + cg * 2];
            float4 w1 = wq4[i * 16 + cg * 2 + 1];
            acc0.x = fmaf(xv, w0.x, acc0.x); acc0.y = fmaf(xv, w0.y, acc0.y);
            acc0.z = fmaf(xv, w0.z, acc0.z); acc0.w = fmaf(xv, w0.w, acc0.w);
            acc1.x = fmaf(xv, w1.x, acc1.x); acc1.y = fmaf(xv, w1.y, acc1.y);
            acc1.z = fmaf(xv, w1.z, acc1.z); acc1.w = fmaf(xv, w1.w, acc1.w);
        }
        float4* qs4 = (float4*)qs;
        qs4[qi * 16 + cg * 2]     = acc0;
        qs4[qi * 16 + cg * 2 + 1] = acc1;
    }
    __syncthreads();

    // --- scores + softmax: each warp does 4 queries (2 pairs) ---
    int warp = t >> 5, lane = t & 31;
    #pragma unroll
    for (int pr = 0; pr < 2; pr++) {
        int qa = warp * 4 + pr * 2;
        float accA[8], accB[8];
        #pragma unroll
        for (int j = 0; j < 8; j++) { accA[j] = 0.f; accB[j] = 0.f; }
        for (int c = 0; c < 64; c++) {
            float va = qs[qa * 64 + c];
            float vb = qs[qa * 64 + 64 + c];
            float4 k0 = ks4[c * 64 + lane * 2];
            float4 k1 = ks4[c * 64 + lane * 2 + 1];
            accA[0] = fmaf(va, k0.x, accA[0]); accA[1] = fmaf(va, k0.y, accA[1]);
            accA[2] = fmaf(va, k0.z, accA[2]); accA[3] = fmaf(va, k0.w, accA[3]);
            accA[4] = fmaf(va, k1.x, accA[4]); accA[5] = fmaf(va, k1.y, accA[5]);
            accA[6] = fmaf(va, k1.z, accA[6]); accA[7] = fmaf(va, k1.w, accA[7]);
            accB[0] = fmaf(vb, k0.x, accB[0]); accB[1] = fmaf(vb, k0.y, accB[1]);
            accB[2] = fmaf(vb, k0.z, accB[2]); accB[3] = fmaf(vb, k0.w, accB[3]);
            accB[4] = fmaf(vb, k1.x, accB[4]); accB[5] = fmaf(vb, k1.y, accB[5]);
            accB[6] = fmaf(vb, k1.z, accB[6]); accB[7] = fmaf(vb, k1.w, accB[7]);
        }
        softmax_write(accA, S, qa, lane);
        softmax_write(accB, S, qa + 1, lane);
    }
    __syncthreads();

    // --- ctx = P @ V : thread -> 2 queries x 4 cols ---
    int tq = t >> 4, tc = t & 15;
    int qi0 = tq * 2;
    float4 c0 = {0,0,0,0}, c1 = {0,0,0,0};
    {
        const float* S0 = S + qi0 * 260;
        for (int j = 0; j < 256; j++) {
            float p0 = S0[j], p1 = S0[260 + j];
            float4 v4 = vs4[j * 16 + tc];
            c0.x = fmaf(p0, v4.x, c0.x); c0.y = fmaf(p0, v4.y, c0.y);
            c0.z = fmaf(p0, v4.z, c0.z); c0.w = fmaf(p0, v4.w, c0.w);
            c1.x = fmaf(p1, v4.x, c1.x); c1.y = fmaf(p1, v4.y, c1.y);
            c1.z = fmaf(p1, v4.z, c1.z); c1.w = fmaf(p1, v4.w, c1.w);
        }
    }
    // stash ctx in qs (safe: qs reads finished before the sync above)
    float4* cs4 = (float4*)qs;
    cs4[qi0 * 16 + tc]       = c0;
    cs4[(qi0 + 1) * 16 + tc] = c1;
    __syncthreads();

    // --- out = ctx @ Wproj + bproj ---
    {
        const float* cs = qs;
        const float4* wp4 = (const float4*)Wp;
        float4 p0 = {0,0,0,0}, p1 = {0,0,0,0};
        for (int i = 0; i < 64; i++) {
            float u0 = cs[qi0 * 64 + i];
            float u1 = cs[qi0 * 64 + 64 + i];
            float4 w = wp4[i * 16 + tc];
            p0.x = fmaf(u0, w.x, p0.x); p0.y = fmaf(u0, w.y, p0.y);
            p0.z = fmaf(u0, w.z, p0.z); p0.w = fmaf(u0, w.w, p0.w);
            p1.x = fmaf(u1, w.x, p1.x); p1.y = fmaf(u1, w.y, p1.y);
            p1.z = fmaf(u1, w.z, p1.z); p1.w = fmaf(u1, w.w, p1.w);
        }
        float4 bb = ((const float4*)bp)[tc];
        p0.x += bb.x; p0.y += bb.y; p0.z += bb.z; p0.w += bb.w;
        p1.x += bb.x; p1.y += bb.y; p1.z += bb.z; p1.w += bb.w;
        float4* out4 = (float4*)out;
        out4[(size_t)(b * NTOK + q0 + qi0) * 16 + tc]     = p0;
        out4[(size_t)(b * NTOK + q0 + qi0 + 1) * 16 + tc] = p1;
    }
}

// ---------------------------------------------------------------------------
extern "C" void kernel_launch(void* const* d_in, const int* in_sizes, int n_in,
                              void* d_out, int out_size) {
    const float* x   = (const float*)d_in[0];
    const float* Wq  = (const float*)d_in[1];
    const float* Wkv = (const float*)d_in[2];
    const float* Wp  = (const float*)d_in[3];
    const float* bp  = (const float*)d_in[4];
    const float* srw = (const float*)d_in[5];
    const float* srb = (const float*)d_in[6];
    const float* lng = (const float*)d_in[7];
    const float* lnb = (const float*)d_in[8];
    float* out = (float*)d_out;

    cudaFuncSetAttribute(k_attn, cudaFuncAttributeMaxDynamicSharedMemorySize, 214016);

    k_transpose_w<<<528, 512>>>(srw);
    k_prep<<<dim3(16, 8), 512>>>(x, srb, lng, lnb, Wkv);
    k_attn<<<dim3(256, 8), 512, 214016>>>(x, Wq, Wp, bp, out);
}

// round 2
// speedup vs baseline: 1.6654x; 1.6654x over previous
#include <cuda_runtime.h>

#define BATCH 8
#define NTOK  16384
#define DIMC  64
#define NK    256
#define SCALE 0.125f

// Scratch (allocation-free rule: __device__ globals)
__device__ float g_w3[32 * 8448];        // staged conv weights: [stage][o][132 pad]
__device__ float g_k[BATCH * 64 * NK];   // k transposed: [b][d][p]
__device__ float g_v[BATCH * NK * 64];   // v: [b][p][c]
__device__ float g_m[BATCH * 64 * NK];   // M = SCALE * Wq @ kT : [b][c][p]
__device__ float g_vp[BATCH * NK * 64];  // V' = v @ Wp : [b][p][e]

// ---------------------------------------------------------------------------
// Kernel 0: reshuffle sr_w [O=64, I=64, KH=8, KW=8] into stage-major padded
// layout so prep-kernel smem fills are linear float4 copies.
// ---------------------------------------------------------------------------
__global__ void k_transpose_w(const float* __restrict__ srw) {
    int d = blockIdx.x * 512 + threadIdx.x;   // 528*512 = 270336 = 32*8448
    int stage = d / 8448;
    int r = d - stage * 8448;
    int o = r / 132;
    int r2 = r - o * 132;
    float v = 0.f;
    if (r2 < 128) {
        int kw = r2 >> 4, ii = r2 & 15;
        int ic = stage >> 3, kh = stage & 7;
        int i = ic * 16 + ii;
        v = srw[o * 4096 + i * 64 + kh * 8 + kw];
    }
    g_w3[d] = v;
}

// ---------------------------------------------------------------------------
// Kernel 1: sr-conv (k=s=8) + LayerNorm + KV projection.
// grid (16 ph, 8 b), 512 threads.
// ---------------------------------------------------------------------------
__global__ void __launch_bounds__(512) k_prep(
    const float* __restrict__ x, const float* __restrict__ srb,
    const float* __restrict__ lng, const float* __restrict__ lnb,
    const float* __restrict__ Wkv)
{
    __shared__ float ws[8448];
    __shared__ float xs[2048];
    int ph = blockIdx.x, b = blockIdx.y;
    int t = threadIdx.x;
    int o = t & 63, pwg = t >> 6;

    float a0 = 0.f, a1 = 0.f;
    const float4* w3_4 = (const float4*)g_w3;
    float4* ws4s = (float4*)ws;
    float4* xs4s = (float4*)xs;

    for (int stage = 0; stage < 32; stage++) {
        int ic = stage >> 3, kh = stage & 7;
        __syncthreads();
        for (int d4 = t; d4 < 2112; d4 += 512)
            ws4s[d4] = w3_4[stage * 2112 + d4];
        {
            int w = t >> 2, j = t & 3;
            int row = (ph * 8 + kh) * 128 + w;
            xs4s[t] = ((const float4*)x)[(b * NTOK + row) * 16 + ic * 4 + j];
        }
        __syncthreads();
        const float4* wsb = (const float4*)ws + o * 33;
        #pragma unroll
        for (int kw = 0; kw < 8; kw++) {
            #pragma unroll
            for (int ii4 = 0; ii4 < 4; ii4++) {
                float4 w  = wsb[kw * 4 + ii4];
                float4 xa = xs4s[(pwg * 8 + kw) * 4 + ii4];
                float4 xb = xs4s[((pwg + 8) * 8 + kw) * 4 + ii4];
                a0 = fmaf(w.x, xa.x, a0); a0 = fmaf(w.y, xa.y, a0);
                a0 = fmaf(w.z, xa.z, a0); a0 = fmaf(w.w, xa.w, a0);
                a1 = fmaf(w.x, xb.x, a1); a1 = fmaf(w.y, xb.y, a1);
                a1 = fmaf(w.z, xb.z, a1); a1 = fmaf(w.w, xb.w, a1);
            }
        }
    }
    __syncthreads();

    float* co = ws;
    float* ln = ws + 1024;
    float bo = srb[o];
    co[pwg * 64 + o]       = a0 + bo;
    co[(pwg + 8) * 64 + o] = a1 + bo;
    __syncthreads();

    int warp = t >> 5, lane = t & 31;
    {
        float v0 = co[warp * 64 + lane];
        float v1 = co[warp * 64 + lane + 32];
        float s = v0 + v1, sq = v0 * v0 + v1 * v1;
        #pragma unroll
        for (int off = 16; off; off >>= 1) {
            s  += __shfl_xor_sync(0xffffffffu, s, off);
            sq += __shfl_xor_sync(0xffffffffu, sq, off);
        }
        float mean = s * (1.f / 64.f);
        float var  = sq * (1.f / 64.f) - mean * mean;
        float rs = rsqrtf(var + 1e-5f);
        ln[warp * 64 + lane]      = (v0 - mean) * rs * lng[lane]      + lnb[lane];
        ln[warp * 64 + lane + 32] = (v1 - mean) * rs * lng[lane + 32] + lnb[lane + 32];
    }
    __syncthreads();

    int c = t & 127, pg = t >> 7;
    float acc[4] = {0.f, 0.f, 0.f, 0.f};
    for (int i = 0; i < 64; i++) {
        float wv = Wkv[i * 128 + c];
        #pragma unroll
        for (int m = 0; m < 4; m++)
            acc[m] = fmaf(ln[(pg * 4 + m) * 64 + i], wv, acc[m]);
    }
    #pragma unroll
    for (int m = 0; m < 4; m++) {
        int p = ph * 16 + pg * 4 + m;
        if (c < 64) g_k[(b * 64 + c) * NK + p]        = acc[m];
        else        g_v[(b * NK + p) * 64 + (c - 64)] = acc[m];
    }
}

// ---------------------------------------------------------------------------
// Kernel 1.5: fold projections into attention operands.
//   z=0: M  = SCALE * Wq @ kT   [64 c][256 p]
//   z=1: V' = v @ Wp            [256 p][64 e]
// grid (8 b, 2 z), 512 threads, 83 KB dyn smem.
// ---------------------------------------------------------------------------
__global__ void __launch_bounds__(512) k_fold(
    const float* __restrict__ Wq, const float* __restrict__ Wp)
{
    extern __shared__ float fs[];
    float* ws = fs;          // 4096 floats
    float* ts = fs + 4096;   // up to 16640 floats
    int b = blockIdx.x, which = blockIdx.y;
    int t = threadIdx.x;
    float4* ws4 = (float4*)ws;
    float4* ts4 = (float4*)ts;

    if (which == 0) {
        const float4* wq4 = (const float4*)Wq;
        const float4* gk4 = (const float4*)g_k + b * 4096;
        for (int i = t; i < 1024; i += 512) ws4[i] = wq4[i];
        for (int i = t; i < 4096; i += 512) ts4[i] = gk4[i];
        __syncthreads();
        int c = t >> 3, pseg = t & 7;
        float4 acc[8];
        #pragma unroll
        for (int i = 0; i < 8; i++) acc[i] = make_float4(0.f, 0.f, 0.f, 0.f);
        for (int d = 0; d < 64; d++) {
            float wv = ws[c * 64 + d];
            #pragma unroll
            for (int i = 0; i < 8; i++) {
                float4 kv = ts4[d * 64 + i * 8 + pseg];
                acc[i].x = fmaf(wv, kv.x, acc[i].x);
                acc[i].y = fmaf(wv, kv.y, acc[i].y);
                acc[i].z = fmaf(wv, kv.z, acc[i].z);
                acc[i].w = fmaf(wv, kv.w, acc[i].w);
            }
        }
        float4* gm4 = (float4*)g_m + b * 4096;
        #pragma unroll
        for (int i = 0; i < 8; i++) {
            acc[i].x *= SCALE; acc[i].y *= SCALE; acc[i].z *= SCALE; acc[i].w *= SCALE;
            gm4[c * 64 + i * 8 + pseg] = acc[i];
        }
    } else {
        const float4* wp4 = (const float4*)Wp;
        const float* gv = g_v + b * 16384;
        for (int i = t; i < 1024; i += 512) ws4[i] = wp4[i];
        for (int idx = t; idx < 16384; idx += 512) {
            int p = idx >> 6, c = idx & 63;
            ts[p * 65 + c] = gv[idx];              // padded rows: conflict-free
        }
        __syncthreads();
        int p = t & 255, eseg = t >> 8;
        float4 acc[8];
        #pragma unroll
        for (int i = 0; i < 8; i++) acc[i] = make_float4(0.f, 0.f, 0.f, 0.f);
        for (int c = 0; c < 64; c++) {
            float vv = ts[p * 65 + c];
            #pragma unroll
            for (int i = 0; i < 8; i++) {
                float4 w = ws4[c * 16 + eseg * 8 + i];
                acc[i].x = fmaf(vv, w.x, acc[i].x);
                acc[i].y = fmaf(vv, w.y, acc[i].y);
                acc[i].z = fmaf(vv, w.z, acc[i].z);
                acc[i].w = fmaf(vv, w.w, acc[i].w);
            }
        }
        float4* gvp4 = (float4*)g_vp + b * 4096;
        #pragma unroll
        for (int i = 0; i < 8; i++)
            gvp4[p * 16 + eseg * 8 + i] = acc[i];
    }
}

// ---------------------------------------------------------------------------
// Kernel 2: scores = x @ M ; softmax ; out = P @ V' + bproj.
// grid (256 qtiles, 8 b), 512 threads, 214 KB dyn smem.
// ---------------------------------------------------------------------------
__device__ __forceinline__ void softmax_write(float* acc, float* S, int qi, int lane) {
    float m = acc[0];
    #pragma unroll
    for (int j = 1; j < 8; j++) m = fmaxf(m, acc[j]);
    #pragma unroll
    for (int off = 16; off; off >>= 1) m = fmaxf(m, __shfl_xor_sync(0xffffffffu, m, off));
    float s = 0.f;
    #pragma unroll
    for (int j = 0; j < 8; j++) { acc[j] = __expf(acc[j] - m); s += acc[j]; }
    #pragma unroll
    for (int off = 16; off; off >>= 1) s += __shfl_xor_sync(0xffffffffu, s, off);
    float inv = 1.f / s;
    float4* S4 = (float4*)S;
    S4[qi * 65 + lane]      = make_float4(acc[0] * inv, acc[1] * inv, acc[2] * inv, acc[3] * inv);
    S4[qi * 65 + 32 + lane] = make_float4(acc[4] * inv, acc[5] * inv, acc[6] * inv, acc[7] * inv);
}

__global__ void __launch_bounds__(512, 1) k_attn(
    const float* __restrict__ x, const float* __restrict__ bp,
    float* __restrict__ out)
{
    extern __shared__ float sm[];
    float* Ms = sm;            // [64 c][256 p]
    float* Vs = sm + 16384;    // [256 p][64 e]
    float* S  = sm + 32768;    // [64 q][260]
    float* xs = sm + 49408;    // [64 q][64 c]

    int t = threadIdx.x;
    int qt = blockIdx.x, b = blockIdx.y;
    int q0 = qt * 64;

    float4* Ms4 = (float4*)Ms;
    float4* Vs4 = (float4*)Vs;
    float4* xs4 = (float4*)xs;
    const float4* gm4  = (const float4*)g_m  + b * 4096;
    const float4* gvp4 = (const float4*)g_vp + b * 4096;
    const float4* gx4  = (const float4*)x + (size_t)(b * NTOK + q0) * 16;
    for (int i = t; i < 4096; i += 512) { Ms4[i] = gm4[i]; Vs4[i] = gvp4[i]; }
    for (int i = t; i < 1024; i += 512) xs4[i] = gx4[i];
    __syncthreads();

    // --- scores + softmax: each warp -> 4 queries, single pass over c ---
    int warp = t >> 5, lane = t & 31;
    {
        int qa = warp * 4;
        float acc[4][8];
        #pragma unroll
        for (int m = 0; m < 4; m++)
            #pragma unroll
            for (int j = 0; j < 8; j++) acc[m][j] = 0.f;
        for (int c = 0; c < 64; c++) {
            float4 k0 = Ms4[c * 64 + lane];       // p = lane*4 .. +3
            float4 k1 = Ms4[c * 64 + 32 + lane];  // p = 128 + lane*4 .. +3
            #pragma unroll
            for (int m = 0; m < 4; m++) {
                float xv = xs[(qa + m) * 64 + c];
                acc[m][0] = fmaf(xv, k0.x, acc[m][0]);
                acc[m][1] = fmaf(xv, k0.y, acc[m][1]);
                acc[m][2] = fmaf(xv, k0.z, acc[m][2]);
                acc[m][3] = fmaf(xv, k0.w, acc[m][3]);
                acc[m][4] = fmaf(xv, k1.x, acc[m][4]);
                acc[m][5] = fmaf(xv, k1.y, acc[m][5]);
                acc[m][6] = fmaf(xv, k1.z, acc[m][6]);
                acc[m][7] = fmaf(xv, k1.w, acc[m][7]);
            }
        }
        #pragma unroll
        for (int m = 0; m < 4; m++)
            softmax_write(acc[m], S, qa + m, lane);
    }
    __syncthreads();

    // --- out = P @ V' + bproj : thread -> 2 queries x 4 cols ---
    int tq = t >> 4, tc = t & 15;
    int qi0 = tq * 2;
    float4 c0 = make_float4(0.f, 0.f, 0.f, 0.f);
    float4 c1 = make_float4(0.f, 0.f, 0.f, 0.f);
    {
        const float* S0 = S + qi0 * 260;
        #pragma unroll 4
        for (int j = 0; j < 256; j++) {
            float p0 = S0[j], p1 = S0[260 + j];
            float4 v4 = Vs4[j * 16 + tc];
            c0.x = fmaf(p0, v4.x, c0.x); c0.y = fmaf(p0, v4.y, c0.y);
            c0.z = fmaf(p0, v4.z, c0.z); c0.w = fmaf(p0, v4.w, c0.w);
            c1.x = fmaf(p1, v4.x, c1.x); c1.y = fmaf(p1, v4.y, c1.y);
            c1.z = fmaf(p1, v4.z, c1.z); c1.w = fmaf(p1, v4.w, c1.w);
        }
    }
    float4 bb = ((const float4*)bp)[tc];
    c0.x += bb.x; c0.y += bb.y; c0.z += bb.z; c0.w += bb.w;
    c1.x += bb.x; c1.y += bb.y; c1.z += bb.z; c1.w += bb.w;
    float4* out4 = (float4*)out;
    out4[(size_t)(b * NTOK + q0 + qi0) * 16 + tc]     = c0;
    out4[(size_t)(b * NTOK + q0 + qi0 + 1) * 16 + tc] = c1;
}

// ---------------------------------------------------------------------------
extern "C" void kernel_launch(void* const* d_in, const int* in_sizes, int n_in,
                              void* d_out, int out_size) {
    const float* x   = (const float*)d_in[0];
    const float* Wq  = (const float*)d_in[1];
    const float* Wkv = (const float*)d_in[2];
    const float* Wp  = (const float*)d_in[3];
    const float* bp  = (const float*)d_in[4];
    const float* srw = (const float*)d_in[5];
    const float* srb = (const float*)d_in[6];
    const float* lng = (const float*)d_in[7];
    const float* lnb = (const float*)d_in[8];
    float* out = (float*)d_out;

    cudaFuncSetAttribute(k_fold, cudaFuncAttributeMaxDynamicSharedMemorySize, 82944);
    cudaFuncSetAttribute(k_attn, cudaFuncAttributeMaxDynamicSharedMemorySize, 214016);

    k_transpose_w<<<528, 512>>>(srw);
    k_prep<<<dim3(16, 8), 512>>>(x, srb, lng, lnb, Wkv);
    k_fold<<<dim3(8, 2), 512, 82944>>>(Wq, Wp);
    k_attn<<<dim3(256, 8), 512, 214016>>>(x, bp, out);
}

// round 4
// speedup vs baseline: 2.4249x; 1.4560x over previous
#include <cuda_runtime.h>
#include <cuda_bf16.h>
#include <cstdint>

#define BATCH 8
#define NTOK  16384
#define NK    256
#define SCALE 0.125f

// ---------------- scratch (allocation-free rule) ----------------
__device__ float    g_w3[32 * 8448];
__device__ float    g_k[BATCH * 64 * NK];    // [b][d][p] fp32
__device__ float    g_v[BATCH * NK * 64];    // [b][p][c] fp32
__device__ uint32_t g_mh[BATCH * 8192];      // M bf16-hi pairs: [c][p/2]
__device__ uint32_t g_ml[BATCH * 8192];      // M bf16-lo
__device__ uint32_t g_vh[BATCH * 8192];      // V' bf16-hi pairs: [p][e/2]
__device__ uint32_t g_vl[BATCH * 8192];      // V' bf16-lo

// ---------------- helpers ----------------
__device__ __forceinline__ uint32_t smem_u32(const void* p) {
    uint32_t a;
    asm("{ .reg .u64 t; cvta.to.shared.u64 t, %1; cvt.u32.u64 %0, t; }" : "=r"(a) : "l"(p));
    return a;
}
__device__ __forceinline__ void split_pair(float a, float b, uint32_t& hp, uint32_t& lp) {
    __nv_bfloat16 ah = __float2bfloat16(a);
    __nv_bfloat16 bh = __float2bfloat16(b);
    __nv_bfloat16 al = __float2bfloat16(a - __bfloat162float(ah));
    __nv_bfloat16 bl = __float2bfloat16(b - __bfloat162float(bh));
    hp = ((uint32_t)__bfloat16_as_ushort(bh) << 16) | (uint32_t)__bfloat16_as_ushort(ah);
    lp = ((uint32_t)__bfloat16_as_ushort(bl) << 16) | (uint32_t)__bfloat16_as_ushort(al);
}

#define LDSM4(r, addr) \
    asm volatile("ldmatrix.sync.aligned.m8n8.x4.shared.b16 {%0,%1,%2,%3}, [%4];" \
        : "=r"((r)[0]), "=r"((r)[1]), "=r"((r)[2]), "=r"((r)[3]) : "r"(addr))
#define LDSM4T(r, addr) \
    asm volatile("ldmatrix.sync.aligned.m8n8.x4.trans.shared.b16 {%0,%1,%2,%3}, [%4];" \
        : "=r"((r)[0]), "=r"((r)[1]), "=r"((r)[2]), "=r"((r)[3]) : "r"(addr))
#define MMA_BF16(d, a, b0, b1) \
    asm volatile("mma.sync.aligned.m16n8k16.row.col.f32.bf16.bf16.f32 " \
        "{%0,%1,%2,%3}, {%4,%5,%6,%7}, {%8,%9}, {%0,%1,%2,%3};" \
        : "+f"((d)[0]), "+f"((d)[1]), "+f"((d)[2]), "+f"((d)[3]) \
        : "r"((a)[0]), "r"((a)[1]), "r"((a)[2]), "r"((a)[3]), "r"(b0), "r"(b1))

// ---------------------------------------------------------------------------
// Kernel 0: weight reshuffle for prep (unchanged)
// ---------------------------------------------------------------------------
__global__ void k_transpose_w(const float* __restrict__ srw) {
    int d = blockIdx.x * 512 + threadIdx.x;
    int stage = d / 8448;
    int r = d - stage * 8448;
    int o = r / 132;
    int r2 = r - o * 132;
    float v = 0.f;
    if (r2 < 128) {
        int kw = r2 >> 4, ii = r2 & 15;
        int ic = stage >> 3, kh = stage & 7;
        v = srw[o * 4096 + (ic * 16 + ii) * 64 + kh * 8 + kw];
    }
    g_w3[d] = v;
}

// ---------------------------------------------------------------------------
// Kernel 1: sr-conv + LayerNorm + KV projection (unchanged)
// ---------------------------------------------------------------------------
__global__ void __launch_bounds__(512) k_prep(
    const float* __restrict__ x, const float* __restrict__ srb,
    const float* __restrict__ lng, const float* __restrict__ lnb,
    const float* __restrict__ Wkv)
{
    __shared__ float ws[8448];
    __shared__ float xs[2048];
    int ph = blockIdx.x, b = blockIdx.y;
    int t = threadIdx.x;
    int o = t & 63, pwg = t >> 6;

    float a0 = 0.f, a1 = 0.f;
    const float4* w3_4 = (const float4*)g_w3;
    float4* ws4s = (float4*)ws;
    float4* xs4s = (float4*)xs;

    for (int stage = 0; stage < 32; stage++) {
        int ic = stage >> 3, kh = stage & 7;
        __syncthreads();
        for (int d4 = t; d4 < 2112; d4 += 512)
            ws4s[d4] = w3_4[stage * 2112 + d4];
        {
            int w = t >> 2, j = t & 3;
            int row = (ph * 8 + kh) * 128 + w;
            xs4s[t] = ((const float4*)x)[(b * NTOK + row) * 16 + ic * 4 + j];
        }
        __syncthreads();
        const float4* wsb = (const float4*)ws + o * 33;
        #pragma unroll
        for (int kw = 0; kw < 8; kw++) {
            #pragma unroll
            for (int ii4 = 0; ii4 < 4; ii4++) {
                float4 w  = wsb[kw * 4 + ii4];
                float4 xa = xs4s[(pwg * 8 + kw) * 4 + ii4];
                float4 xb = xs4s[((pwg + 8) * 8 + kw) * 4 + ii4];
                a0 = fmaf(w.x, xa.x, a0); a0 = fmaf(w.y, xa.y, a0);
                a0 = fmaf(w.z, xa.z, a0); a0 = fmaf(w.w, xa.w, a0);
                a1 = fmaf(w.x, xb.x, a1); a1 = fmaf(w.y, xb.y, a1);
                a1 = fmaf(w.z, xb.z, a1); a1 = fmaf(w.w, xb.w, a1);
            }
        }
    }
    __syncthreads();

    float* co = ws;
    float* ln = ws + 1024;
    float bo = srb[o];
    co[pwg * 64 + o]       = a0 + bo;
    co[(pwg + 8) * 64 + o] = a1 + bo;
    __syncthreads();

    int warp = t >> 5, lane = t & 31;
    {
        float v0 = co[warp * 64 + lane];
        float v1 = co[warp * 64 + lane + 32];
        float s = v0 + v1, sq = v0 * v0 + v1 * v1;
        #pragma unroll
        for (int off = 16; off; off >>= 1) {
            s  += __shfl_xor_sync(0xffffffffu, s, off);
            sq += __shfl_xor_sync(0xffffffffu, sq, off);
        }
        float mean = s * (1.f / 64.f);
        float var  = sq * (1.f / 64.f) - mean * mean;
        float rs = rsqrtf(var + 1e-5f);
        ln[warp * 64 + lane]      = (v0 - mean) * rs * lng[lane]      + lnb[lane];
        ln[warp * 64 + lane + 32] = (v1 - mean) * rs * lng[lane + 32] + lnb[lane + 32];
    }
    __syncthreads();

    int c = t & 127, pg = t >> 7;
    float acc[4] = {0.f, 0.f, 0.f, 0.f};
    for (int i = 0; i < 64; i++) {
        float wv = Wkv[i * 128 + c];
        #pragma unroll
        for (int m = 0; m < 4; m++)
            acc[m] = fmaf(ln[(pg * 4 + m) * 64 + i], wv, acc[m]);
    }
    #pragma unroll
    for (int m = 0; m < 4; m++) {
        int p = ph * 16 + pg * 4 + m;
        if (c < 64) g_k[(b * 64 + c) * NK + p]        = acc[m];
        else        g_v[(b * NK + p) * 64 + (c - 64)] = acc[m];
    }
}

// ---------------------------------------------------------------------------
// Kernel 1.5: fold projections -> bf16 hi/lo pair-packed operands.
//   z=0: M[c][p] = SCALE * sum_d Wq[c*64+d] * k[d][p]   pairs along p
//   z=1: V'[p][e] = sum_c v[p][c] * Wp[c*64+e]          pairs along e
// ---------------------------------------------------------------------------
__global__ void __launch_bounds__(512) k_fold(
    const float* __restrict__ Wq, const float* __restrict__ Wp)
{
    extern __shared__ float fs[];
    int b = blockIdx.x, z = blockIdx.y;
    int t = threadIdx.x;

    if (z == 0) {
        float* wq = fs;           // [64 c][64 d]
        float* ks = fs + 4096;    // [64 d][256 p]
        for (int i = t; i < 1024; i += 512) ((float4*)wq)[i] = ((const float4*)Wq)[i];
        const float4* gk4 = (const float4*)g_k + b * 4096;
        for (int i = t; i < 4096; i += 512) ((float4*)ks)[i] = gk4[i];
        __syncthreads();
        uint32_t* mh = g_mh + b * 8192;
        uint32_t* ml = g_ml + b * 8192;
        for (int idx = t; idx < 8192; idx += 512) {
            int c = idx >> 7, pp = idx & 127;
            float m0 = 0.f, m1 = 0.f;
            for (int d = 0; d < 64; d++) {
                float w = wq[c * 64 + d];
                m0 = fmaf(w, ks[d * 256 + 2 * pp],     m0);
                m1 = fmaf(w, ks[d * 256 + 2 * pp + 1], m1);
            }
            m0 *= SCALE; m1 *= SCALE;
            uint32_t hp, lp; split_pair(m0, m1, hp, lp);
            mh[idx] = hp; ml[idx] = lp;
        }
    } else {
        float* wp = fs;           // [64 c][64 e]
        float* vs = fs + 4096;    // [256 p][65]
        for (int i = t; i < 1024; i += 512) ((float4*)wp)[i] = ((const float4*)Wp)[i];
        const float* gv = g_v + b * 16384;
        for (int i = t; i < 16384; i += 512) { int p = i >> 6, c = i & 63; vs[p * 65 + c] = gv[i]; }
        __syncthreads();
        uint32_t* vh = g_vh + b * 8192;
        uint32_t* vl = g_vl + b * 8192;
        for (int idx = t; idx < 8192; idx += 512) {
            int p = idx >> 5, ee = idx & 31;
            float a0 = 0.f, a1 = 0.f;
            for (int c = 0; c < 64; c++) {
                float v = vs[p * 65 + c];
                a0 = fmaf(v, wp[c * 64 + 2 * ee],     a0);
                a1 = fmaf(v, wp[c * 64 + 2 * ee + 1], a1);
            }
            uint32_t hp, lp; split_pair(a0, a1, hp, lp);
            vh[idx] = hp; vl[idx] = lp;
        }
    }
}

// ---------------------------------------------------------------------------
// Kernel 2: HMMA attention. 128 queries/CTA, grid (128, 8), 512 threads.
// SMEM byte map (dynamic):
//   E region [0, 135168): phase1 aliases A1h@0(18432) A1l@18432 B1h@36864(33792) B1l@70656
//                         phase2: Eh@0 (128*528=67584) El@67584
//   B2h@135168 (256*144=36864)  B2l@172032
//   PSUM@208896: [128 rows][4 wc] fp32 = 2048   -> total 210944
// ---------------------------------------------------------------------------
#define SA1 144
#define SB1 528
#define SE  528
#define SB2 144
#define A1H_ 0
#define A1L_ 18432
#define B1H_ 36864
#define B1L_ 70656
#define EH_  0
#define EL_  67584
#define B2H_ 135168
#define B2L_ 172032
#define PSUM_ 208896
#define SMEM_ASK 210944

__global__ void __launch_bounds__(512, 1) k_attn_mma(
    const float* __restrict__ x, const float* __restrict__ bp,
    float* __restrict__ out)
{
    extern __shared__ char sm[];
    uint32_t sb = smem_u32(sm);
    int t = threadIdx.x;
    int L = t & 31, w = t >> 5;
    int qt = blockIdx.x, b = blockIdx.y;
    int q0 = qt * 128;

    // ---- copy B1 (M) and B2 (V') hi/lo into padded smem ----
    {
        const uint4* mh = (const uint4*)(g_mh + b * 8192);
        const uint4* ml = (const uint4*)(g_ml + b * 8192);
        const uint4* vh = (const uint4*)(g_vh + b * 8192);
        const uint4* vl = (const uint4*)(g_vl + b * 8192);
        uint4* b1h = (uint4*)(sm + B1H_);
        uint4* b1l = (uint4*)(sm + B1L_);
        uint4* b2h = (uint4*)(sm + B2H_);
        uint4* b2l = (uint4*)(sm + B2L_);
        for (int i = t; i < 2048; i += 512) {
            int r1 = i >> 5, c1 = i & 31;           // M rows: 32 uint4 data, stride 33
            b1h[r1 * 33 + c1] = mh[i];
            b1l[r1 * 33 + c1] = ml[i];
            int r2 = i >> 3, c2 = i & 7;            // V' rows: 8 uint4 data, stride 9
            b2h[r2 * 9 + c2] = vh[i];
            b2l[r2 * 9 + c2] = vl[i];
        }
    }
    // ---- A1: x tile fp32 -> bf16 hi/lo, rows stride 144B ----
    {
        int q = t >> 2, seg = t & 3;
        const float4* xg = (const float4*)(x + ((size_t)b * NTOK + q0 + q) * 64 + seg * 16);
        uint32_t* ah = (uint32_t*)(sm + A1H_);
        uint32_t* al = (uint32_t*)(sm + A1L_);
        int wb = q * 36 + seg * 8;
        #pragma unroll
        for (int j = 0; j < 4; j++) {
            float4 v = xg[j];
            uint32_t hp, lp;
            split_pair(v.x, v.y, hp, lp);
            ah[wb + 2 * j] = hp; al[wb + 2 * j] = lp;
            split_pair(v.z, v.w, hp, lp);
            ah[wb + 2 * j + 1] = hp; al[wb + 2 * j + 1] = lp;
        }
    }
    __syncthreads();

    int wr = w >> 2, wc = w & 3;
    int m0 = wr * 32;

    // ================= GEMM1: S[128,256] = x @ M (3-term bf16) =================
    float acc[2][8][4];
    #pragma unroll
    for (int i = 0; i < 2; i++)
        #pragma unroll
        for (int j = 0; j < 8; j++)
            #pragma unroll
            for (int k = 0; k < 4; k++) acc[i][j][k] = 0.f;

    {
        int n0 = wc * 64;
        uint32_t a_lane = (uint32_t)((L & 15) * SA1 + (L >> 4) * 16);
        uint32_t b_lane = (uint32_t)(((L & 7) + 8 * ((L >> 3) & 1)) * SB1 + (L >> 4) * 16);
        const int aoffs[3] = {A1H_, A1L_, A1H_};
        const int boffs[3] = {B1H_, B1H_, B1L_};
        #pragma unroll
        for (int term = 0; term < 3; term++) {
            uint32_t abase = sb + aoffs[term] + m0 * SA1 + a_lane;
            uint32_t bbase = sb + boffs[term] + n0 * 2 + b_lane;
            #pragma unroll
            for (int kc = 0; kc < 4; kc++) {
                uint32_t af[2][4];
                LDSM4(af[0], abase + kc * 32);
                LDSM4(af[1], abase + 16 * SA1 + kc * 32);
                uint32_t bf[4][4];
                #pragma unroll
                for (int j = 0; j < 4; j++)
                    LDSM4T(bf[j], bbase + kc * 16 * SB1 + j * 32);
                #pragma unroll
                for (int i = 0; i < 2; i++)
                    #pragma unroll
                    for (int j = 0; j < 4; j++) {
                        MMA_BF16(acc[i][2 * j],     af[i], bf[j][0], bf[j][1]);
                        MMA_BF16(acc[i][2 * j + 1], af[i], bf[j][2], bf[j][3]);
                    }
            }
        }
    }
    __syncthreads();   // all GEMM1 reads of A1/B1 done before E overwrites region

    // ================= exp + row sums + store E (bf16 hi/lo) =================
    {
        int n0 = wc * 64;
        float rs[4] = {0.f, 0.f, 0.f, 0.f};
        #pragma unroll
        for (int i = 0; i < 2; i++) {
            int r0 = m0 + i * 16 + (L >> 2);
            #pragma unroll
            for (int j = 0; j < 8; j++) {
                float e0 = __expf(acc[i][j][0]);
                float e1 = __expf(acc[i][j][1]);
                float e2 = __expf(acc[i][j][2]);
                float e3 = __expf(acc[i][j][3]);
                rs[i * 2]     += e0 + e1;
                rs[i * 2 + 1] += e2 + e3;
                int cb = (n0 + j * 8 + 2 * (L & 3)) * 2;
                uint32_t hp, lp;
                split_pair(e0, e1, hp, lp);
                *(uint32_t*)(sm + EH_ + r0 * SE + cb) = hp;
                *(uint32_t*)(sm + EL_ + r0 * SE + cb) = lp;
                split_pair(e2, e3, hp, lp);
                *(uint32_t*)(sm + EH_ + (r0 + 8) * SE + cb) = hp;
                *(uint32_t*)(sm + EL_ + (r0 + 8) * SE + cb) = lp;
            }
        }
        #pragma unroll
        for (int k = 0; k < 4; k++) {
            rs[k] += __shfl_xor_sync(0xffffffffu, rs[k], 1);
            rs[k] += __shfl_xor_sync(0xffffffffu, rs[k], 2);
        }
        if ((L & 3) == 0) {
            float* ps = (float*)(sm + PSUM_);
            #pragma unroll
            for (int i = 0; i < 2; i++)
                #pragma unroll
                for (int h = 0; h < 2; h++) {
                    int row = m0 + i * 16 + 8 * h + (L >> 2);
                    ps[row * 4 + wc] = rs[i * 2 + h];
                }
        }
    }
    __syncthreads();

    // ================= GEMM2: ctx[128,64] = E @ V' (3-term bf16) ===============
    float acc2[2][2][4];
    #pragma unroll
    for (int i = 0; i < 2; i++)
        #pragma unroll
        for (int j = 0; j < 2; j++)
            #pragma unroll
            for (int k = 0; k < 4; k++) acc2[i][j][k] = 0.f;

    {
        int n2 = wc * 16;
        uint32_t a_lane = (uint32_t)((L & 15) * SE + (L >> 4) * 16);
        uint32_t b_lane = (uint32_t)(((L & 7) + 8 * ((L >> 3) & 1)) * SB2 + (L >> 4) * 16);
        const int aoffs[3] = {EH_, EL_, EH_};
        const int boffs[3] = {B2H_, B2H_, B2L_};
        #pragma unroll
        for (int term = 0; term < 3; term++) {
            uint32_t abase = sb + aoffs[term] + m0 * SE + a_lane;
            uint32_t bbase = sb + boffs[term] + n2 * 2 + b_lane;
            #pragma unroll
            for (int kc = 0; kc < 16; kc++) {
                uint32_t af[2][4];
                LDSM4(af[0], abase + kc * 32);
                LDSM4(af[1], abase + 16 * SE + kc * 32);
                uint32_t bf[4];
                LDSM4T(bf, bbase + kc * 16 * SB2);
                MMA_BF16(acc2[0][0], af[0], bf[0], bf[1]);
                MMA_BF16(acc2[0][1], af[0], bf[2], bf[3]);
                MMA_BF16(acc2[1][0], af[1], bf[0], bf[1]);
                MMA_BF16(acc2[1][1], af[1], bf[2], bf[3]);
            }
        }
    }

    // ================= epilogue: /rowsum + bias + store =================
    {
        int n2 = wc * 16;
        const float* ps = (const float*)(sm + PSUM_);
        #pragma unroll
        for (int i = 0; i < 2; i++)
            #pragma unroll
            for (int h = 0; h < 2; h++) {
                int row = m0 + i * 16 + 8 * h + (L >> 2);
                float4 p4 = *(const float4*)(ps + row * 4);
                float inv = 1.f / (p4.x + p4.y + p4.z + p4.w);
                float* og = out + ((size_t)(b * NTOK) + q0 + row) * 64;
                #pragma unroll
                for (int jj = 0; jj < 2; jj++) {
                    int c = n2 + jj * 8 + 2 * (L & 3);
                    float2 bb = *(const float2*)(bp + c);
                    float2 o;
                    o.x = acc2[i][jj][2 * h]     * inv + bb.x;
                    o.y = acc2[i][jj][2 * h + 1] * inv + bb.y;
                    *(float2*)(og + c) = o;
                }
            }
    }
}

// ---------------------------------------------------------------------------
extern "C" void kernel_launch(void* const* d_in, const int* in_sizes, int n_in,
                              void* d_out, int out_size) {
    const float* x   = (const float*)d_in[0];
    const float* Wq  = (const float*)d_in[1];
    const float* Wkv = (const float*)d_in[2];
    const float* Wp  = (const float*)d_in[3];
    const float* bp  = (const float*)d_in[4];
    const float* srw = (const float*)d_in[5];
    const float* srb = (const float*)d_in[6];
    const float* lng = (const float*)d_in[7];
    const float* lnb = (const float*)d_in[8];
    float* out = (float*)d_out;

    cudaFuncSetAttribute(k_fold, cudaFuncAttributeMaxDynamicSharedMemorySize, 82944);
    cudaFuncSetAttribute(k_attn_mma, cudaFuncAttributeMaxDynamicSharedMemorySize, SMEM_ASK);

    k_transpose_w<<<528, 512>>>(srw);
    k_prep<<<dim3(16, 8), 512>>>(x, srb, lng, lnb, Wkv);
    k_fold<<<dim3(8, 2), 512, 82944>>>(Wq, Wp);
    k_attn_mma<<<dim3(128, 8), 512, SMEM_ASK>>>(x, bp, out);
}